// round 5
// baseline (speedup 1.0000x reference)
#include <cuda_runtime.h>
#include <math.h>

// ---------------- problem constants ----------------
#define NB   16
#define NL   4097        // x0 rows / batch
#define NMR  1025        // x1 rows / batch
#define NSR  4097        // x2 rows / batch
#define DS   256
#define DM   512
#define DL   1024
#define NK1  1025        // att1 softmax length
#define NK2  4098        // att2 / proj length
#define GS   64          // splits per batch for streaming pass
#define RPB  65          // ceil(4097/64)
#define SPL1 16          // m-splits for t1 = Wk1^T q1
#define SPL2 32          // m-splits for t2 = Wk2^T q2

// ---------------- scratch (__device__ globals; no allocation) ----------------
__device__ __align__(16) float g_csp [NB*DM];
__device__ __align__(16) float g_cmp [NB*DL];
__device__ __align__(16) float g_q1  [NB*DM];
__device__ __align__(16) float g_q2  [NB*DL];
__device__ __align__(16) float g_t1  [NB*DM];
__device__ __align__(16) float g_t2  [NB*DL];
__device__ __align__(16) float g_pT1 [SPL1*NB*DM];
__device__ __align__(16) float g_pT2 [SPL2*NB*DL];
__device__ __align__(16) float g_l1  [NB*NK1];
__device__ __align__(16) float g_a1sT[NK1*NB];      // transposed: [n][b]
__device__ __align__(16) float g_a1p [NB*NK2];
__device__ __align__(16) float g_pm  [NB*GS];
__device__ __align__(16) float g_pz  [NB*GS];
__device__ __align__(16) float g_pe  [(size_t)NB*GS*DL];
__device__ __align__(16) float g_pa  [(size_t)NB*GS*DL];
__device__ __align__(16) float g_s   [NB*DL];
__device__ __align__(16) float g_outv[NB*DL];
__device__ __align__(16) float g_gs  [NB*DS];

// ---------------- helpers ----------------
__device__ __forceinline__ float wredsum(float v) {
#pragma unroll
    for (int o = 16; o > 0; o >>= 1) v += __shfl_xor_sync(0xffffffffu, v, o);
    return v;
}
__device__ __forceinline__ float wredmax(float v) {
#pragma unroll
    for (int o = 16; o > 0; o >>= 1) v = fmaxf(v, __shfl_xor_sync(0xffffffffu, v, o));
    return v;
}
__device__ __forceinline__ float block_sum(float v, float* red) {
    int l = threadIdx.x & 31, w = threadIdx.x >> 5;
    v = wredsum(v);
    if (l == 0) red[w] = v;
    __syncthreads();
    float t = red[0]+red[1]+red[2]+red[3]+red[4]+red[5]+red[6]+red[7];
    __syncthreads();
    return t;
}
__device__ __forceinline__ float block_max(float v, float* red) {
    int l = threadIdx.x & 31, w = threadIdx.x >> 5;
    v = wredmax(v);
    if (l == 0) red[w] = v;
    __syncthreads();
    float t = fmaxf(fmaxf(fmaxf(red[0],red[1]),fmaxf(red[2],red[3])),
                    fmaxf(fmaxf(red[4],red[5]),fmaxf(red[6],red[7])));
    __syncthreads();
    return t;
}

// ---------------------------------------------------------------------------
// Batched matvec: Y[b*M + m] = bias[m] + sum_d W[m,d] * X[b*ldx + d], b=0..15.
// One warp per output row, 16 batches in registers. D % 128 == 0.
// ---------------------------------------------------------------------------
__global__ __launch_bounds__(256) void k_bmv(
    const float* __restrict__ W, const float* __restrict__ X,
    const float* __restrict__ bias, float* __restrict__ Y,
    int M, int D, int ldx)
{
    int m = blockIdx.x * 8 + (threadIdx.x >> 5);
    int lane = threadIdx.x & 31;
    if (m >= M) return;
    const float4* W4 = reinterpret_cast<const float4*>(W + (size_t)m * D);
    const float4* X4 = reinterpret_cast<const float4*>(X);
    int D4 = D >> 2, ldx4 = ldx >> 2;
    float acc[16];
#pragma unroll
    for (int b = 0; b < 16; b++) acc[b] = 0.f;
    for (int i = lane; i < D4; i += 32) {
        float4 w = __ldg(&W4[i]);
#pragma unroll
        for (int b = 0; b < 16; b++) {
            float4 x = __ldg(&X4[b * ldx4 + i]);
            acc[b] += w.x*x.x + w.y*x.y + w.z*x.z + w.w*x.w;
        }
    }
    float keep = 0.f;
#pragma unroll
    for (int b = 0; b < 16; b++) {
        float v = wredsum(acc[b]);
        if (lane == b) keep = v;
    }
    if (lane < 16) Y[lane * M + m] = keep + (bias ? __ldg(&bias[m]) : 0.f);
}

// ---------------------------------------------------------------------------
// Transposed matvec partials: part[s][b][d] = sum_{m in split s} W[m,d]*Q[b*M+m]
// Block covers all D (256 threads * VD). grid.x = splits.
// ---------------------------------------------------------------------------
template<int VD>
__global__ __launch_bounds__(256) void k_bmvT(
    const float* __restrict__ W, const float* __restrict__ Q,
    float* __restrict__ part, int M, int D, int mper)
{
    int d0 = threadIdx.x * VD;
    int m0 = blockIdx.x * mper;
    int m1 = min(m0 + mper, M);
    float acc[16][VD];
#pragma unroll
    for (int b = 0; b < 16; b++)
#pragma unroll
        for (int v = 0; v < VD; v++) acc[b][v] = 0.f;
    for (int m = m0; m < m1; m++) {
        const float* wrow = W + (size_t)m * D + d0;
        float wv[VD];
        if (VD == 4) { float4 t = *reinterpret_cast<const float4*>(wrow);
                       wv[0]=t.x; wv[1]=t.y; wv[2]=t.z; wv[3]=t.w; }
        else         { float2 t = *reinterpret_cast<const float2*>(wrow);
                       wv[0]=t.x; wv[1]=t.y; }
#pragma unroll
        for (int b = 0; b < 16; b++) {
            float qv = __ldg(&Q[b * M + m]);
#pragma unroll
            for (int v = 0; v < VD; v++) acc[b][v] += qv * wv[v];
        }
    }
#pragma unroll
    for (int b = 0; b < 16; b++)
#pragma unroll
        for (int v = 0; v < VD; v++)
            part[((size_t)blockIdx.x * 16 + b) * D + d0 + v] = acc[b][v];
}

__global__ void k_reduceT(const float* __restrict__ part, float* __restrict__ T,
                          int D, int S, float scale)
{
    int d = blockIdx.x * 256 + threadIdx.x;
    int b = blockIdx.y;
    if (d >= D) return;
    float a = 0.f;
    for (int s = 0; s < S; s++) a += part[((size_t)s * 16 + b) * D + d];
    T[b * D + d] = a * scale;
}

// ---------------------------------------------------------------------------
// logits1 rows: l1[b][1+r] = t1[b] . x1[b][1+r][:]   (t1 already has /22 folded)
// ---------------------------------------------------------------------------
__global__ __launch_bounds__(256) void k_logits1(const float* __restrict__ x1)
{
    int b = blockIdx.y;
    int w = threadIdx.x >> 5, lane = threadIdx.x & 31;
    const float4* t14 = reinterpret_cast<const float4*>(g_t1 + b * DM);
    float4 t0 = __ldg(&t14[lane]);
    float4 t1v = __ldg(&t14[lane + 32]);
    float4 t2v = __ldg(&t14[lane + 64]);
    float4 t3v = __ldg(&t14[lane + 96]);
#pragma unroll
    for (int j = 0; j < 8; j++) {
        int r = blockIdx.x * 64 + j * 8 + w;
        const float4* xr = reinterpret_cast<const float4*>(
            x1 + ((size_t)b * NMR + 1 + r) * DM);
        float4 a = __ldg(&xr[lane]);
        float s = a.x*t0.x + a.y*t0.y + a.z*t0.z + a.w*t0.w;
        a = __ldg(&xr[lane + 32]); s += a.x*t1v.x + a.y*t1v.y + a.z*t1v.z + a.w*t1v.w;
        a = __ldg(&xr[lane + 64]); s += a.x*t2v.x + a.y*t2v.y + a.z*t2v.z + a.w*t2v.w;
        a = __ldg(&xr[lane + 96]); s += a.x*t3v.x + a.y*t3v.y + a.z*t3v.z + a.w*t3v.w;
        s = wredsum(s);
        if (lane == 0) g_l1[b * NK1 + 1 + r] = s;
    }
}

// ---------------------------------------------------------------------------
// softmax1 per batch: l0 = t1.csp; softmax over [l0, l1[1..1024]]; write a1sT[n][b]
// ---------------------------------------------------------------------------
__global__ __launch_bounds__(256) void k_softmax1()
{
    __shared__ float red[8];
    int b = blockIdx.x, tid = threadIdx.x;
    float p = 0.f;
    for (int i = tid; i < DM; i += 256) p += g_t1[b*DM+i] * g_csp[b*DM+i];
    float l0 = block_sum(p, red);
    float mx = -1e30f;
    for (int i = tid; i < NK1; i += 256) {
        float v = i ? g_l1[b*NK1+i] : l0;
        mx = fmaxf(mx, v);
    }
    mx = block_max(mx, red);
    float se = 0.f;
    for (int i = tid; i < NK1; i += 256) {
        float v = i ? g_l1[b*NK1+i] : l0;
        se += __expf(v - mx);
    }
    se = block_sum(se, red);
    float inv = 1.f / se;
    for (int i = tid; i < NK1; i += 256) {
        float v = i ? g_l1[b*NK1+i] : l0;
        g_a1sT[i * 16 + b] = __expf(v - mx) * inv;
    }
}

// ---------------------------------------------------------------------------
// att1 proj: a1p[b][m] = proj_b[m] + sum_n proj_w[m][n] * a1s[b][n]
// ---------------------------------------------------------------------------
__global__ __launch_bounds__(256) void k_proj(
    const float* __restrict__ proj_w, const float* __restrict__ proj_b)
{
    int m = blockIdx.x * 8 + (threadIdx.x >> 5);
    int lane = threadIdx.x & 31;
    if (m >= NK2) return;
    const float* pw = proj_w + (size_t)m * NK1;
    float acc[16];
#pragma unroll
    for (int b = 0; b < 16; b++) acc[b] = 0.f;
    for (int n = lane; n < NK1; n += 32) {
        float w = __ldg(&pw[n]);
        const float4* a4 = reinterpret_cast<const float4*>(g_a1sT + n * 16);
        float4 v0 = __ldg(a4+0), v1 = __ldg(a4+1), v2 = __ldg(a4+2), v3 = __ldg(a4+3);
        acc[0]+=w*v0.x; acc[1]+=w*v0.y; acc[2] +=w*v0.z; acc[3] +=w*v0.w;
        acc[4]+=w*v1.x; acc[5]+=w*v1.y; acc[6] +=w*v1.z; acc[7] +=w*v1.w;
        acc[8]+=w*v2.x; acc[9]+=w*v2.y; acc[10]+=w*v2.z; acc[11]+=w*v2.w;
        acc[12]+=w*v3.x; acc[13]+=w*v3.y; acc[14]+=w*v3.z; acc[15]+=w*v3.w;
    }
    float keep = 0.f;
#pragma unroll
    for (int b = 0; b < 16; b++) {
        float v = wredsum(acc[b]);
        if (lane == b) keep = v;
    }
    if (lane < 16) g_a1p[lane * NK2 + m] = keep + __ldg(&proj_b[m]);
}

// ---------------------------------------------------------------------------
// Streaming pass over x0 (the big one): per (batch, split) block, online-
// softmax logits2 plus two weighted row-sum accumulators; emit partials.
// ---------------------------------------------------------------------------
__global__ __launch_bounds__(256) void k_stream(const float* __restrict__ x0)
{
    __shared__ float red[8];
    int b = blockIdx.y, g = blockIdx.x;
    int tid = threadIdx.x, lane = tid & 31, wid = tid >> 5;
    int r0 = g * RPB, r1 = min(r0 + RPB, NL);
    float4 t2v = __ldg(reinterpret_cast<const float4*>(g_t2 + b * DL) + tid);
    float m = -1e30f, z = 0.f;
    float ae0=0,ae1=0,ae2=0,ae3=0, aa0=0,aa1=0,aa2=0,aa3=0;
    const float4* xb = reinterpret_cast<const float4*>(x0 + (size_t)b * NL * DL);
    float4 r = __ldg(&xb[(size_t)r0 * 256 + tid]);
    for (int k = r0; k < r1; k++) {
        float4 rn = (k + 1 < r1) ? __ldg(&xb[(size_t)(k + 1) * 256 + tid])
                                 : make_float4(0.f,0.f,0.f,0.f);
        float d = r.x*t2v.x + r.y*t2v.y + r.z*t2v.z + r.w*t2v.w;
        d = wredsum(d);
        __syncthreads();
        if (lane == 0) red[wid] = d;
        __syncthreads();
        float l = red[0]+red[1]+red[2]+red[3]+red[4]+red[5]+red[6]+red[7];
        float a1 = __ldg(&g_a1p[b * NK2 + 1 + k]);
        float nm = fmaxf(m, l);
        float sc = __expf(m - nm);
        float p  = __expf(l - nm);
        z = z * sc + p;
        ae0 = ae0*sc + p*r.x; ae1 = ae1*sc + p*r.y;
        ae2 = ae2*sc + p*r.z; ae3 = ae3*sc + p*r.w;
        aa0 += a1*r.x; aa1 += a1*r.y; aa2 += a1*r.z; aa3 += a1*r.w;
        m = nm; r = rn;
    }
    size_t o = ((size_t)b * GS + g) * DL + tid * 4;
    g_pe[o+0]=ae0; g_pe[o+1]=ae1; g_pe[o+2]=ae2; g_pe[o+3]=ae3;
    g_pa[o+0]=aa0; g_pa[o+1]=aa1; g_pa[o+2]=aa2; g_pa[o+3]=aa3;
    if (tid == 0) { g_pm[b*GS+g] = m; g_pz[b*GS+g] = z; }
}

// ---------------------------------------------------------------------------
// Combine partials + k=0 (cls_m_proj) term: s = 0.3*sa + 0.7*se/Z
// ---------------------------------------------------------------------------
__global__ __launch_bounds__(256) void k_combine()
{
    __shared__ float red[8];
    __shared__ float ws[GS];
    int b = blockIdx.x, tid = threadIdx.x;
    const float4* t24 = reinterpret_cast<const float4*>(g_t2 + b * DL);
    const float4* c4  = reinterpret_cast<const float4*>(g_cmp + b * DL);
    float4 tv = t24[tid], cv = c4[tid];
    float p = tv.x*cv.x + tv.y*cv.y + tv.z*cv.z + tv.w*cv.w;
    float l2c = block_sum(p, red);
    float M = l2c;
#pragma unroll 8
    for (int g = 0; g < GS; g++) M = fmaxf(M, g_pm[b*GS+g]);
    if (tid < GS) ws[tid] = __expf(g_pm[b*GS+tid] - M);
    __syncthreads();
    float ecls = __expf(l2c - M);
    float Z = ecls;
#pragma unroll 8
    for (int g = 0; g < GS; g++) Z += ws[g] * g_pz[b*GS+g];
    float se0=0,se1=0,se2=0,se3=0, sa0=0,sa1=0,sa2=0,sa3=0;
    for (int g = 0; g < GS; g++) {
        float w = ws[g];
        size_t o = ((size_t)b * GS + g) * DL;
        float4 e = __ldg(reinterpret_cast<const float4*>(g_pe + o) + tid);
        float4 a = __ldg(reinterpret_cast<const float4*>(g_pa + o) + tid);
        se0 += w*e.x; se1 += w*e.y; se2 += w*e.z; se3 += w*e.w;
        sa0 += a.x;   sa1 += a.y;   sa2 += a.z;   sa3 += a.w;
    }
    float a10 = g_a1p[b * NK2 + 0];
    se0 += ecls*cv.x; se1 += ecls*cv.y; se2 += ecls*cv.z; se3 += ecls*cv.w;
    sa0 += a10*cv.x;  sa1 += a10*cv.y;  sa2 += a10*cv.z;  sa3 += a10*cv.w;
    float invZ = 1.f / Z;
    float4 sv;
    sv.x = 0.3f*sa0 + 0.7f*se0*invZ;
    sv.y = 0.3f*sa1 + 0.7f*se1*invZ;
    sv.z = 0.3f*sa2 + 0.7f*se2*invZ;
    sv.w = 0.3f*sa3 + 0.7f*se3*invZ;
    reinterpret_cast<float4*>(g_s + b * DL)[tid] = sv;
}

// ---------------------------------------------------------------------------
// Output: all 4097 rows of each batch equal g_s[b] (att3 softmax over size-1
// axis is identically 1).
// ---------------------------------------------------------------------------
__global__ void k_write(float4* __restrict__ out)
{
    const float4* g4 = reinterpret_cast<const float4*>(g_gs);
    size_t total = (size_t)NB * NL * (DS / 4);
    for (size_t i = (size_t)blockIdx.x * blockDim.x + threadIdx.x; i < total;
         i += (size_t)gridDim.x * blockDim.x) {
        size_t row = i >> 6;              // 64 float4 per 256-float row
        int b = (int)(row / NL);
        int d4 = (int)(i & 63);
        out[i] = __ldg(&g4[b * 64 + d4]);
    }
}

// ---------------------------------------------------------------------------
extern "C" void kernel_launch(void* const* d_in, const int* in_sizes, int n_in,
                              void* d_out, int out_size)
{
    const float* x0     = (const float*)d_in[0];
    const float* x1     = (const float*)d_in[1];
    const float* x2     = (const float*)d_in[2];
    const float* f_s_w  = (const float*)d_in[3];
    const float* f_s_b  = (const float*)d_in[4];
    const float* f_m_w  = (const float*)d_in[5];
    const float* f_m_b  = (const float*)d_in[6];
    const float* Wq1    = (const float*)d_in[7];
    const float* Wk1    = (const float*)d_in[8];
    const float* Wq2    = (const float*)d_in[9];
    const float* Wk2    = (const float*)d_in[10];
    const float* Wv     = (const float*)d_in[11];
    const float* proj_w = (const float*)d_in[12];
    const float* proj_b = (const float*)d_in[13];
    const float* gs_w   = (const float*)d_in[14];
    const float* gs_b   = (const float*)d_in[15];

    float *csp, *cmp, *q1, *q2, *t1, *t2, *pT1, *pT2, *s, *outv, *gs;
    cudaGetSymbolAddress((void**)&csp,  g_csp);
    cudaGetSymbolAddress((void**)&cmp,  g_cmp);
    cudaGetSymbolAddress((void**)&q1,   g_q1);
    cudaGetSymbolAddress((void**)&q2,   g_q2);
    cudaGetSymbolAddress((void**)&t1,   g_t1);
    cudaGetSymbolAddress((void**)&t2,   g_t2);
    cudaGetSymbolAddress((void**)&pT1,  g_pT1);
    cudaGetSymbolAddress((void**)&pT2,  g_pT2);
    cudaGetSymbolAddress((void**)&s,    g_s);
    cudaGetSymbolAddress((void**)&outv, g_outv);
    cudaGetSymbolAddress((void**)&gs,   g_gs);

    // cls_s_proj = f_s_w . x2[:,0,:] + f_s_b        (512x256)
    k_bmv<<<DM/8, 256>>>(f_s_w, x2, f_s_b, csp, DM, DS, NSR*DS);
    // cls_m_proj = f_m_w . x1[:,0,:] + f_m_b        (1024x512)
    k_bmv<<<DL/8, 256>>>(f_m_w, x1, f_m_b, cmp, DL, DM, NMR*DM);
    // q1 = Wq1 . csp                                 (512x512)
    k_bmv<<<DM/8, 256>>>(Wq1, csp, nullptr, q1, DM, DM, DM);
    // q2 = Wq2 . cmp                                 (1024x1024)
    k_bmv<<<DL/8, 256>>>(Wq2, cmp, nullptr, q2, DL, DL, DL);
    // t1 = (Wk1^T q1) / 22
    k_bmvT<2><<<SPL1, 256>>>(Wk1, q1, pT1, DM, DM, DM / SPL1);
    k_reduceT<<<dim3(DM/256, NB), 256>>>(pT1, t1, DM, SPL1, 1.f/22.f);
    // t2 = (Wk2^T q2) / 32
    k_bmvT<4><<<SPL2, 256>>>(Wk2, q2, pT2, DL, DL, DL / SPL2);
    k_reduceT<<<dim3(DL/256, NB), 256>>>(pT2, t2, DL, SPL2, 1.f/32.f);
    // att1 logits over p_m rows, softmax, then proj_w projection
    k_logits1<<<dim3(16, NB), 256>>>(x1);
    k_softmax1<<<NB, 256>>>();
    k_proj<<<(NK2 + 7) / 8, 256>>>(proj_w, proj_b);
    // single pass over x0: logits2 (online softmax) + both weighted row-sums
    k_stream<<<dim3(GS, NB), 256>>>(x0);
    k_combine<<<NB, 256>>>();
    // out = Wv . s ; g_s = gs_w . out + gs_b
    k_bmv<<<DL/8, 256>>>(Wv, s, nullptr, outv, DL, DL, DL);
    k_bmv<<<DS/8, 256>>>(gs_w, outv, gs_b, gs, DS, DL, DL);
    // broadcast write of the full output
    k_write<<<8192, 256>>>((float4*)d_out);
}

// round 6
// speedup vs baseline: 1.1437x; 1.1437x over previous
#include <cuda_runtime.h>
#include <math.h>

// ---------------- problem constants ----------------
#define NB   16
#define NL   4097        // x0 rows / batch
#define NMR  1025        // x1 rows / batch
#define NSR  4097        // x2 rows / batch
#define DS   256
#define DM   512
#define DL   1024
#define NK1  1025        // att1 softmax length
#define NK2  4098        // att2 / proj length
#define GS   64          // splits per batch for streaming pass
#define RPB  65          // ceil(4097/64)
#define INV22f (1.0f/22.0f)
#define INV32f (1.0f/32.0f)

// ---------------- scratch (__device__ globals; no allocation) ----------------
__device__ __align__(16) float g_csp [NB*DM];
__device__ __align__(16) float g_cmp [NB*DL];
__device__ __align__(16) float g_t1  [NB*DM];
__device__ __align__(16) float g_pT2 [2*NB*DL];     // [b*2+h][1024], unscaled
__device__ __align__(16) float g_l1  [NB*NK1];
__device__ __align__(16) float g_a1sT[NK1*NB];      // transposed: [n][b]
__device__ __align__(16) float g_a1p [NB*NK2];
__device__ __align__(16) float g_pm  [NB*GS];
__device__ __align__(16) float g_pz  [NB*GS];
__device__ __align__(16) float g_pe  [(size_t)NB*GS*DL];
__device__ __align__(16) float g_pa  [(size_t)NB*GS*DL];
__device__ __align__(16) float g_pgs [2*NB*DS];     // [b*2+h][256], no bias

// ---------------- helpers ----------------
__device__ __forceinline__ float wredsum(float v) {
#pragma unroll
    for (int o = 16; o > 0; o >>= 1) v += __shfl_xor_sync(0xffffffffu, v, o);
    return v;
}
__device__ __forceinline__ float wredmax(float v) {
#pragma unroll
    for (int o = 16; o > 0; o >>= 1) v = fmaxf(v, __shfl_xor_sync(0xffffffffu, v, o));
    return v;
}
__device__ __forceinline__ float dot4(float4 a, float4 b) {
    return a.x*b.x + a.y*b.y + a.z*b.z + a.w*b.w;
}
// block_sum for 256-thread blocks (8 warps)
__device__ __forceinline__ float block_sum8(float v, float* red) {
    int l = threadIdx.x & 31, w = threadIdx.x >> 5;
    v = wredsum(v);
    if (l == 0) red[w] = v;
    __syncthreads();
    float t = red[0]+red[1]+red[2]+red[3]+red[4]+red[5]+red[6]+red[7];
    __syncthreads();
    return t;
}
__device__ __forceinline__ float block_max8(float v, float* red) {
    int l = threadIdx.x & 31, w = threadIdx.x >> 5;
    v = wredmax(v);
    if (l == 0) red[w] = v;
    __syncthreads();
    float t = fmaxf(fmaxf(fmaxf(red[0],red[1]),fmaxf(red[2],red[3])),
                    fmaxf(fmaxf(red[4],red[5]),fmaxf(red[6],red[7])));
    __syncthreads();
    return t;
}

// ---------------------------------------------------------------------------
// Fused prologue. grid=48, block=1024.
//  blocks 0..15  (b = blockIdx.x): chain A for batch b:
//      csp = f_s_w.x2cls + b  -> q1 = Wq1.csp -> t1 = (Wk1^T q1)/22
//      (csp also written to g_csp for softmax1's l0 term)
//  blocks 16..47 (idx = blockIdx.x-16, b = idx>>1, h = idx&1): chain B:
//      cmp = f_m_w.x1cls + b (full, h==0 writes g_cmp)
//      q2 rows [h*512, h*512+512) = Wq2.cmp     (smem)
//      t2 partial over this m-half -> g_pT2[idx]  (consumers add halves, /32)
// All intermediates live in shared memory; weights are re-read per block but
// served from L2 (16-way reuse).
// ---------------------------------------------------------------------------
__global__ __launch_bounds__(1024) void k_pro(
    const float* __restrict__ x1, const float* __restrict__ x2,
    const float* __restrict__ f_s_w, const float* __restrict__ f_s_b,
    const float* __restrict__ f_m_w, const float* __restrict__ f_m_b,
    const float* __restrict__ Wq1, const float* __restrict__ Wk1,
    const float* __restrict__ Wq2, const float* __restrict__ Wk2)
{
    __shared__ float  sA[1024];
    __shared__ float  sB[1024];
    __shared__ float4 sP[1024];
    int tid = threadIdx.x, lane = tid & 31, w = tid >> 5;

    if (blockIdx.x < 16) {
        int b = blockIdx.x;
        // ---- phase 1: csp[512] ----
        const float4* xc = reinterpret_cast<const float4*>(x2 + (size_t)b * NSR * DS);
        float4 xa = __ldg(&xc[lane]), xb = __ldg(&xc[lane + 32]);
        for (int m = w; m < DM; m += 32) {
            const float4* wr = reinterpret_cast<const float4*>(f_s_w + (size_t)m * DS);
            float d = dot4(__ldg(&wr[lane]), xa) + dot4(__ldg(&wr[lane + 32]), xb);
            d = wredsum(d);
            if (lane == 0) {
                d += __ldg(&f_s_b[m]);
                sA[m] = d;
                g_csp[b * DM + m] = d;
            }
        }
        __syncthreads();
        // ---- phase 2: q1[512] = Wq1 . csp ----
        {
            const float4* s4 = reinterpret_cast<const float4*>(sA);
            float4 x0v = s4[lane], x1v = s4[lane+32], x2v = s4[lane+64], x3v = s4[lane+96];
            for (int m = w; m < DM; m += 32) {
                const float4* wr = reinterpret_cast<const float4*>(Wq1 + (size_t)m * DM);
                float d = dot4(__ldg(&wr[lane]),    x0v) + dot4(__ldg(&wr[lane+32]), x1v)
                        + dot4(__ldg(&wr[lane+64]), x2v) + dot4(__ldg(&wr[lane+96]), x3v);
                d = wredsum(d);
                if (lane == 0) sB[m] = d;
            }
        }
        __syncthreads();
        // ---- phase 3: t1[d] = (1/22) sum_m Wk1[m][d] * q1[m] ----
        {
            int d4 = tid & 127, part = tid >> 7;   // 8 parts x 64 m
            float4 acc = make_float4(0.f, 0.f, 0.f, 0.f);
            int m0 = part * 64;
#pragma unroll 8
            for (int mm = 0; mm < 64; mm++) {
                int m = m0 + mm;
                float4 wv = __ldg(reinterpret_cast<const float4*>(Wk1 + (size_t)m * DM) + d4);
                float q = sB[m];
                acc.x += q*wv.x; acc.y += q*wv.y; acc.z += q*wv.z; acc.w += q*wv.w;
            }
            sP[part * 128 + d4] = acc;
        }
        __syncthreads();
        if (tid < 128) {
            float4 a = sP[tid];
#pragma unroll
            for (int p = 1; p < 8; p++) {
                float4 c = sP[p * 128 + tid];
                a.x += c.x; a.y += c.y; a.z += c.z; a.w += c.w;
            }
            a.x *= INV22f; a.y *= INV22f; a.z *= INV22f; a.w *= INV22f;
            reinterpret_cast<float4*>(g_t1 + b * DM)[tid] = a;
        }
    } else {
        int idx = blockIdx.x - 16, b = idx >> 1, h = idx & 1;
        // ---- phase 1: cmp[1024] (full) ----
        const float4* xc = reinterpret_cast<const float4*>(x1 + (size_t)b * NMR * DM);
        float4 xr[4];
#pragma unroll
        for (int k = 0; k < 4; k++) xr[k] = __ldg(&xc[lane + 32 * k]);
        for (int m = w; m < DL; m += 32) {
            const float4* wr = reinterpret_cast<const float4*>(f_m_w + (size_t)m * DM);
            float d = 0.f;
#pragma unroll
            for (int k = 0; k < 4; k++) d += dot4(__ldg(&wr[lane + 32 * k]), xr[k]);
            d = wredsum(d);
            if (lane == 0) {
                d += __ldg(&f_m_b[m]);
                sA[m] = d;
                if (h == 0) g_cmp[b * DL + m] = d;
            }
        }
        __syncthreads();
        // ---- phase 2: q2 rows [h*512, h*512+512) ----
        {
            const float4* s4 = reinterpret_cast<const float4*>(sA);
            float4 xv[8];
#pragma unroll
            for (int k = 0; k < 8; k++) xv[k] = s4[lane + 32 * k];
            for (int m = h * 512 + w; m < h * 512 + 512; m += 32) {
                const float4* wr = reinterpret_cast<const float4*>(Wq2 + (size_t)m * DL);
                float d = 0.f;
#pragma unroll
                for (int k = 0; k < 8; k++) d += dot4(__ldg(&wr[lane + 32 * k]), xv[k]);
                d = wredsum(d);
                if (lane == 0) sB[m - h * 512] = d;
            }
        }
        __syncthreads();
        // ---- phase 3: t2 partial over this half's m ----
        {
            int d4 = tid & 255, part = tid >> 8;   // 4 parts x 128 m
            float4 acc = make_float4(0.f, 0.f, 0.f, 0.f);
            int m0 = h * 512 + part * 128;
#pragma unroll 8
            for (int mm = 0; mm < 128; mm++) {
                int m = m0 + mm;
                float4 wv = __ldg(reinterpret_cast<const float4*>(Wk2 + (size_t)m * DL) + d4);
                float q = sB[m - h * 512];
                acc.x += q*wv.x; acc.y += q*wv.y; acc.z += q*wv.z; acc.w += q*wv.w;
            }
            sP[part * 256 + d4] = acc;
        }
        __syncthreads();
        if (tid < 256) {
            float4 a = sP[tid];
#pragma unroll
            for (int p = 1; p < 4; p++) {
                float4 c = sP[p * 256 + tid];
                a.x += c.x; a.y += c.y; a.z += c.z; a.w += c.w;
            }
            reinterpret_cast<float4*>(g_pT2 + (size_t)idx * DL)[tid] = a;
        }
    }
}

// ---------------------------------------------------------------------------
// logits1 rows: l1[b][1+r] = t1[b] . x1[b][1+r][:]   (t1 has /22 folded)
// ---------------------------------------------------------------------------
__global__ __launch_bounds__(256) void k_logits1(const float* __restrict__ x1)
{
    int b = blockIdx.y;
    int w = threadIdx.x >> 5, lane = threadIdx.x & 31;
    const float4* t14 = reinterpret_cast<const float4*>(g_t1 + b * DM);
    float4 t0 = __ldg(&t14[lane]);
    float4 t1v = __ldg(&t14[lane + 32]);
    float4 t2v = __ldg(&t14[lane + 64]);
    float4 t3v = __ldg(&t14[lane + 96]);
#pragma unroll
    for (int j = 0; j < 8; j++) {
        int r = blockIdx.x * 64 + j * 8 + w;
        const float4* xr = reinterpret_cast<const float4*>(
            x1 + ((size_t)b * NMR + 1 + r) * DM);
        float s = dot4(__ldg(&xr[lane]),      t0)
                + dot4(__ldg(&xr[lane + 32]), t1v)
                + dot4(__ldg(&xr[lane + 64]), t2v)
                + dot4(__ldg(&xr[lane + 96]), t3v);
        s = wredsum(s);
        if (lane == 0) g_l1[b * NK1 + 1 + r] = s;
    }
}

// ---------------------------------------------------------------------------
// softmax1 per batch: l0 = t1.csp; softmax over [l0, l1[1..1024]] -> a1sT[n][b]
// ---------------------------------------------------------------------------
__global__ __launch_bounds__(256) void k_softmax1()
{
    __shared__ float red[8];
    int b = blockIdx.x, tid = threadIdx.x;
    float p = 0.f;
    for (int i = tid; i < DM; i += 256) p += g_t1[b*DM+i] * g_csp[b*DM+i];
    float l0 = block_sum8(p, red);
    float mx = -1e30f;
    for (int i = tid; i < NK1; i += 256) {
        float v = i ? g_l1[b*NK1+i] : l0;
        mx = fmaxf(mx, v);
    }
    mx = block_max8(mx, red);
    float se = 0.f;
    for (int i = tid; i < NK1; i += 256) {
        float v = i ? g_l1[b*NK1+i] : l0;
        se += __expf(v - mx);
    }
    se = block_sum8(se, red);
    float inv = 1.f / se;
    for (int i = tid; i < NK1; i += 256) {
        float v = i ? g_l1[b*NK1+i] : l0;
        g_a1sT[i * 16 + b] = __expf(v - mx) * inv;
    }
}

// ---------------------------------------------------------------------------
// att1 proj: a1p[b][m] = proj_b[m] + sum_n proj_w[m][n] * a1s[b][n]
// ---------------------------------------------------------------------------
__global__ __launch_bounds__(256) void k_proj(
    const float* __restrict__ proj_w, const float* __restrict__ proj_b)
{
    int m = blockIdx.x * 8 + (threadIdx.x >> 5);
    int lane = threadIdx.x & 31;
    if (m >= NK2) return;
    const float* pw = proj_w + (size_t)m * NK1;
    float acc[16];
#pragma unroll
    for (int b = 0; b < 16; b++) acc[b] = 0.f;
    for (int n = lane; n < NK1; n += 32) {
        float w = __ldg(&pw[n]);
        const float4* a4 = reinterpret_cast<const float4*>(g_a1sT + n * 16);
        float4 v0 = __ldg(a4+0), v1 = __ldg(a4+1), v2 = __ldg(a4+2), v3 = __ldg(a4+3);
        acc[0]+=w*v0.x; acc[1]+=w*v0.y; acc[2] +=w*v0.z; acc[3] +=w*v0.w;
        acc[4]+=w*v1.x; acc[5]+=w*v1.y; acc[6] +=w*v1.z; acc[7] +=w*v1.w;
        acc[8]+=w*v2.x; acc[9]+=w*v2.y; acc[10]+=w*v2.z; acc[11]+=w*v2.w;
        acc[12]+=w*v3.x; acc[13]+=w*v3.y; acc[14]+=w*v3.z; acc[15]+=w*v3.w;
    }
    float keep = 0.f;
#pragma unroll
    for (int b = 0; b < 16; b++) {
        float v = wredsum(acc[b]);
        if (lane == b) keep = v;
    }
    if (lane < 16) g_a1p[lane * NK2 + m] = keep + __ldg(&proj_b[m]);
}

// ---------------------------------------------------------------------------
// Streaming pass over x0: per (batch, split) block, online-softmax of logits2
// plus the att1-weighted row-sum; emit partials. t2 is reconstructed from the
// two unscaled halves (g_pT2) with the /32 folded in.
// ---------------------------------------------------------------------------
__global__ __launch_bounds__(256) void k_stream(const float* __restrict__ x0)
{
    __shared__ float red[8];
    int b = blockIdx.y, g = blockIdx.x;
    int tid = threadIdx.x, lane = tid & 31, wid = tid >> 5;
    int r0 = g * RPB, r1 = min(r0 + RPB, NL);
    float4 e0 = __ldg(reinterpret_cast<const float4*>(g_pT2 + (size_t)(b*2+0) * DL) + tid);
    float4 e1 = __ldg(reinterpret_cast<const float4*>(g_pT2 + (size_t)(b*2+1) * DL) + tid);
    float4 t2v = make_float4((e0.x+e1.x)*INV32f, (e0.y+e1.y)*INV32f,
                             (e0.z+e1.z)*INV32f, (e0.w+e1.w)*INV32f);
    float m = -1e30f, z = 0.f;
    float ae0=0,ae1=0,ae2=0,ae3=0, aa0=0,aa1=0,aa2=0,aa3=0;
    const float4* xb = reinterpret_cast<const float4*>(x0 + (size_t)b * NL * DL);
    float4 r = __ldg(&xb[(size_t)r0 * 256 + tid]);
    for (int k = r0; k < r1; k++) {
        float4 rn = (k + 1 < r1) ? __ldg(&xb[(size_t)(k + 1) * 256 + tid])
                                 : make_float4(0.f,0.f,0.f,0.f);
        float d = dot4(r, t2v);
        d = wredsum(d);
        __syncthreads();
        if (lane == 0) red[wid] = d;
        __syncthreads();
        float l = red[0]+red[1]+red[2]+red[3]+red[4]+red[5]+red[6]+red[7];
        float a1 = __ldg(&g_a1p[b * NK2 + 1 + k]);
        float nm = fmaxf(m, l);
        float sc = __expf(m - nm);
        float p  = __expf(l - nm);
        z = z * sc + p;
        ae0 = ae0*sc + p*r.x; ae1 = ae1*sc + p*r.y;
        ae2 = ae2*sc + p*r.z; ae3 = ae3*sc + p*r.w;
        aa0 += a1*r.x; aa1 += a1*r.y; aa2 += a1*r.z; aa3 += a1*r.w;
        m = nm; r = rn;
    }
    size_t o = ((size_t)b * GS + g) * DL + tid * 4;
    g_pe[o+0]=ae0; g_pe[o+1]=ae1; g_pe[o+2]=ae2; g_pe[o+3]=ae3;
    g_pa[o+0]=aa0; g_pa[o+1]=aa1; g_pa[o+2]=aa2; g_pa[o+3]=aa3;
    if (tid == 0) { g_pm[b*GS+g] = m; g_pz[b*GS+g] = z; }
}

// ---------------------------------------------------------------------------
// Fused epilogue. grid=32 (2 blocks/batch: b = blockIdx.x>>1, h = &1).
// Each block: combine split-softmax partials -> s (smem, full 1024),
// outv rows [h*512,+512) = Wv.s (smem), then partial gs over its outv-half:
// g_pgs[b*2+h][m] = gs_w[m, h*512:+512] . outv_half.  (bias added in k_write)
// ---------------------------------------------------------------------------
__global__ __launch_bounds__(1024) void k_final(
    const float* __restrict__ Wv, const float* __restrict__ gs_w)
{
    __shared__ float sS[1024];
    __shared__ float sO[512];
    __shared__ float red[32];
    __shared__ float ws[GS];
    int tid = threadIdx.x, lane = tid & 31, w = tid >> 5;
    int b = blockIdx.x >> 1, h = blockIdx.x & 1;

    float t2d = (__ldg(&g_pT2[(size_t)(b*2+0)*DL + tid]) +
                 __ldg(&g_pT2[(size_t)(b*2+1)*DL + tid])) * INV32f;
    float cv = __ldg(&g_cmp[b * DL + tid]);
    // l2c = t2 . cmp  (block reduce over 32 warps)
    float p = t2d * cv;
    p = wredsum(p);
    if (lane == 0) red[w] = p;
    __syncthreads();
    if (w == 0) {
        float t = red[lane];
        t = wredsum(t);
        if (lane == 0) red[0] = t;
    }
    __syncthreads();
    float l2c = red[0];
    float M = l2c;
#pragma unroll 8
    for (int g = 0; g < GS; g++) M = fmaxf(M, __ldg(&g_pm[b*GS+g]));
    if (tid < GS) ws[tid] = __expf(g_pm[b*GS+tid] - M);
    __syncthreads();
    float ecls = __expf(l2c - M);
    float Z = ecls;
#pragma unroll 8
    for (int g = 0; g < GS; g++) Z += ws[g] * __ldg(&g_pz[b*GS+g]);
    float se = 0.f, sa = 0.f;
    for (int g = 0; g < GS; g++) {
        size_t o = ((size_t)b * GS + g) * DL + tid;
        se += ws[g] * __ldg(&g_pe[o]);
        sa += __ldg(&g_pa[o]);
    }
    float a10 = __ldg(&g_a1p[b * NK2]);
    se += ecls * cv;
    sa += a10 * cv;
    sS[tid] = 0.3f * sa + 0.7f * se / Z;
    __syncthreads();
    // outv half = Wv[rows h*512..] . s
    {
        const float4* s4 = reinterpret_cast<const float4*>(sS);
        float4 xv[8];
#pragma unroll
        for (int k = 0; k < 8; k++) xv[k] = s4[lane + 32 * k];
        for (int m = h * 512 + w; m < h * 512 + 512; m += 32) {
            const float4* wr = reinterpret_cast<const float4*>(Wv + (size_t)m * DL);
            float d = 0.f;
#pragma unroll
            for (int k = 0; k < 8; k++) d += dot4(__ldg(&wr[lane + 32 * k]), xv[k]);
            d = wredsum(d);
            if (lane == 0) sO[m - h * 512] = d;
        }
    }
    __syncthreads();
    // partial gs over this outv-half
    {
        const float4* s4 = reinterpret_cast<const float4*>(sO);
        float4 xv[4];
#pragma unroll
        for (int k = 0; k < 4; k++) xv[k] = s4[lane + 32 * k];
        for (int m = w; m < DS; m += 32) {
            const float4* wr = reinterpret_cast<const float4*>(
                gs_w + (size_t)m * DL + h * 512);
            float d = 0.f;
#pragma unroll
            for (int k = 0; k < 4; k++) d += dot4(__ldg(&wr[lane + 32 * k]), xv[k]);
            d = wredsum(d);
            if (lane == 0) g_pgs[(size_t)(b*2+h) * DS + m] = d;
        }
    }
}

// ---------------------------------------------------------------------------
// Broadcast write: out[b][n][:] = pgs[b*2][:] + pgs[b*2+1][:] + gs_b[:]
// for all 4097 rows n (att3 softmax over a size-1 axis is identically 1,
// and row 0 is g_s itself).
// ---------------------------------------------------------------------------
__global__ void k_write(float4* __restrict__ out, const float* __restrict__ gs_b)
{
    const float4* p4 = reinterpret_cast<const float4*>(g_pgs);
    const float4* b4 = reinterpret_cast<const float4*>(gs_b);
    unsigned total = (unsigned)NB * NL * (DS / 4);
    for (unsigned i = blockIdx.x * blockDim.x + threadIdx.x; i < total;
         i += gridDim.x * blockDim.x) {
        unsigned row = i >> 6;            // 64 float4 per 256-float row
        unsigned b = row / NL;
        unsigned d4 = i & 63;
        float4 v0 = __ldg(&p4[(b * 2 + 0) * 64 + d4]);
        float4 v1 = __ldg(&p4[(b * 2 + 1) * 64 + d4]);
        float4 bb = __ldg(&b4[d4]);
        out[i] = make_float4(v0.x + v1.x + bb.x, v0.y + v1.y + bb.y,
                             v0.z + v1.z + bb.z, v0.w + v1.w + bb.w);
    }
}

// ---------------------------------------------------------------------------
extern "C" void kernel_launch(void* const* d_in, const int* in_sizes, int n_in,
                              void* d_out, int out_size)
{
    const float* x0     = (const float*)d_in[0];
    const float* x1     = (const float*)d_in[1];
    const float* x2     = (const float*)d_in[2];
    const float* f_s_w  = (const float*)d_in[3];
    const float* f_s_b  = (const float*)d_in[4];
    const float* f_m_w  = (const float*)d_in[5];
    const float* f_m_b  = (const float*)d_in[6];
    const float* Wq1    = (const float*)d_in[7];
    const float* Wk1    = (const float*)d_in[8];
    const float* Wq2    = (const float*)d_in[9];
    const float* Wk2    = (const float*)d_in[10];
    const float* Wv     = (const float*)d_in[11];
    const float* proj_w = (const float*)d_in[12];
    const float* proj_b = (const float*)d_in[13];
    const float* gs_w   = (const float*)d_in[14];
    const float* gs_b   = (const float*)d_in[15];

    // fused prologue: csp/q1/t1 (blocks 0-15) + cmp/q2/t2-partials (16-47)
    k_pro<<<48, 1024>>>(x1, x2, f_s_w, f_s_b, f_m_w, f_m_b, Wq1, Wk1, Wq2, Wk2);
    // att1 logits over p_m rows, softmax, proj_w projection
    k_logits1<<<dim3(16, NB), 256>>>(x1);
    k_softmax1<<<NB, 256>>>();
    k_proj<<<(NK2 + 7) / 8, 256>>>(proj_w, proj_b);
    // single pass over x0: logits2 (online softmax) + att1-weighted row sums
    k_stream<<<dim3(GS, NB), 256>>>(x0);
    // fused epilogue: combine -> s -> Wv.s -> partial gs
    k_final<<<2 * NB, 1024>>>(Wv, gs_w);
    // broadcast write (adds gs halves + bias)
    k_write<<<8192, 256>>>((float4*)d_out, gs_b);
}

// round 7
// speedup vs baseline: 1.2256x; 1.0716x over previous
#include <cuda_runtime.h>
#include <math.h>

// ---------------- problem constants ----------------
#define NB   16
#define NL   4097        // x0 rows / batch
#define NMR  1025        // x1 rows / batch
#define NSR  4097        // x2 rows / batch
#define DS   256
#define DM   512
#define DL   1024
#define NK1  1025        // att1 softmax length
#define NK2  4098        // att2 / proj length
#define GS   64          // splits per batch for streaming pass
#define RPB  65          // ceil(4097/64)
#define INV22f (1.0f/22.0f)
#define INV32f (1.0f/32.0f)

// ---------------- scratch (__device__ globals; no allocation) ----------------
__device__ __align__(16) float g_csp [NB*DM];
__device__ __align__(16) float g_cmp [NB*DL];
__device__ __align__(16) float g_t1  [NB*DM];
__device__ __align__(16) float g_pT2 [2*NB*DL];     // [b*2+h][1024], unscaled
__device__ __align__(16) float g_l1  [NB*NK1];
__device__ __align__(16) float g_a1sT[NK1*NB];      // transposed: [n][b]
__device__ __align__(16) float g_a1p [NB*NK2];
__device__ __align__(16) float g_pm  [NB*GS];
__device__ __align__(16) float g_pz  [NB*GS];
__device__ __align__(16) float g_pe  [(size_t)NB*GS*DL];
__device__ __align__(16) float g_pa  [(size_t)NB*GS*DL];
__device__ __align__(16) float g_pgs [2*NB*DS];     // [b*2+h][256], no bias

// ---------------- helpers ----------------
__device__ __forceinline__ float wredsum(float v) {
#pragma unroll
    for (int o = 16; o > 0; o >>= 1) v += __shfl_xor_sync(0xffffffffu, v, o);
    return v;
}
__device__ __forceinline__ float wredmax(float v) {
#pragma unroll
    for (int o = 16; o > 0; o >>= 1) v = fmaxf(v, __shfl_xor_sync(0xffffffffu, v, o));
    return v;
}
__device__ __forceinline__ float dot4(float4 a, float4 b) {
    return a.x*b.x + a.y*b.y + a.z*b.z + a.w*b.w;
}
__device__ __forceinline__ float block_sum8(float v, float* red) {
    int l = threadIdx.x & 31, w = threadIdx.x >> 5;
    v = wredsum(v);
    if (l == 0) red[w] = v;
    __syncthreads();
    float t = red[0]+red[1]+red[2]+red[3]+red[4]+red[5]+red[6]+red[7];
    __syncthreads();
    return t;
}
__device__ __forceinline__ float block_max8(float v, float* red) {
    int l = threadIdx.x & 31, w = threadIdx.x >> 5;
    v = wredmax(v);
    if (l == 0) red[w] = v;
    __syncthreads();
    float t = fmaxf(fmaxf(fmaxf(red[0],red[1]),fmaxf(red[2],red[3])),
                    fmaxf(fmaxf(red[4],red[5]),fmaxf(red[6],red[7])));
    __syncthreads();
    return t;
}

// ---------------------------------------------------------------------------
// Fused prologue. grid=48, block=1024.  (unchanged from R6)
//  blocks 0..15:  csp -> q1 -> t1 (/22)  for batch b
//  blocks 16..47: cmp -> q2 half -> t2 partial (g_pT2, consumers add + /32)
// ---------------------------------------------------------------------------
__global__ __launch_bounds__(1024) void k_pro(
    const float* __restrict__ x1, const float* __restrict__ x2,
    const float* __restrict__ f_s_w, const float* __restrict__ f_s_b,
    const float* __restrict__ f_m_w, const float* __restrict__ f_m_b,
    const float* __restrict__ Wq1, const float* __restrict__ Wk1,
    const float* __restrict__ Wq2, const float* __restrict__ Wk2)
{
    __shared__ float  sA[1024];
    __shared__ float  sB[1024];
    __shared__ float4 sP[1024];
    int tid = threadIdx.x, lane = tid & 31, w = tid >> 5;

    if (blockIdx.x < 16) {
        int b = blockIdx.x;
        const float4* xc = reinterpret_cast<const float4*>(x2 + (size_t)b * NSR * DS);
        float4 xa = __ldg(&xc[lane]), xb = __ldg(&xc[lane + 32]);
        for (int m = w; m < DM; m += 32) {
            const float4* wr = reinterpret_cast<const float4*>(f_s_w + (size_t)m * DS);
            float d = dot4(__ldg(&wr[lane]), xa) + dot4(__ldg(&wr[lane + 32]), xb);
            d = wredsum(d);
            if (lane == 0) {
                d += __ldg(&f_s_b[m]);
                sA[m] = d;
                g_csp[b * DM + m] = d;
            }
        }
        __syncthreads();
        {
            const float4* s4 = reinterpret_cast<const float4*>(sA);
            float4 x0v = s4[lane], x1v = s4[lane+32], x2v = s4[lane+64], x3v = s4[lane+96];
            for (int m = w; m < DM; m += 32) {
                const float4* wr = reinterpret_cast<const float4*>(Wq1 + (size_t)m * DM);
                float d = dot4(__ldg(&wr[lane]),    x0v) + dot4(__ldg(&wr[lane+32]), x1v)
                        + dot4(__ldg(&wr[lane+64]), x2v) + dot4(__ldg(&wr[lane+96]), x3v);
                d = wredsum(d);
                if (lane == 0) sB[m] = d;
            }
        }
        __syncthreads();
        {
            int d4 = tid & 127, part = tid >> 7;
            float4 acc = make_float4(0.f, 0.f, 0.f, 0.f);
            int m0 = part * 64;
#pragma unroll 8
            for (int mm = 0; mm < 64; mm++) {
                int m = m0 + mm;
                float4 wv = __ldg(reinterpret_cast<const float4*>(Wk1 + (size_t)m * DM) + d4);
                float q = sB[m];
                acc.x += q*wv.x; acc.y += q*wv.y; acc.z += q*wv.z; acc.w += q*wv.w;
            }
            sP[part * 128 + d4] = acc;
        }
        __syncthreads();
        if (tid < 128) {
            float4 a = sP[tid];
#pragma unroll
            for (int p = 1; p < 8; p++) {
                float4 c = sP[p * 128 + tid];
                a.x += c.x; a.y += c.y; a.z += c.z; a.w += c.w;
            }
            a.x *= INV22f; a.y *= INV22f; a.z *= INV22f; a.w *= INV22f;
            reinterpret_cast<float4*>(g_t1 + b * DM)[tid] = a;
        }
    } else {
        int idx = blockIdx.x - 16, b = idx >> 1, h = idx & 1;
        const float4* xc = reinterpret_cast<const float4*>(x1 + (size_t)b * NMR * DM);
        float4 xr[4];
#pragma unroll
        for (int k = 0; k < 4; k++) xr[k] = __ldg(&xc[lane + 32 * k]);
        for (int m = w; m < DL; m += 32) {
            const float4* wr = reinterpret_cast<const float4*>(f_m_w + (size_t)m * DM);
            float d = 0.f;
#pragma unroll
            for (int k = 0; k < 4; k++) d += dot4(__ldg(&wr[lane + 32 * k]), xr[k]);
            d = wredsum(d);
            if (lane == 0) {
                d += __ldg(&f_m_b[m]);
                sA[m] = d;
                if (h == 0) g_cmp[b * DL + m] = d;
            }
        }
        __syncthreads();
        {
            const float4* s4 = reinterpret_cast<const float4*>(sA);
            float4 xv[8];
#pragma unroll
            for (int k = 0; k < 8; k++) xv[k] = s4[lane + 32 * k];
            for (int m = h * 512 + w; m < h * 512 + 512; m += 32) {
                const float4* wr = reinterpret_cast<const float4*>(Wq2 + (size_t)m * DL);
                float d = 0.f;
#pragma unroll
                for (int k = 0; k < 8; k++) d += dot4(__ldg(&wr[lane + 32 * k]), xv[k]);
                d = wredsum(d);
                if (lane == 0) sB[m - h * 512] = d;
            }
        }
        __syncthreads();
        {
            int d4 = tid & 255, part = tid >> 8;
            float4 acc = make_float4(0.f, 0.f, 0.f, 0.f);
            int m0 = h * 512 + part * 128;
#pragma unroll 8
            for (int mm = 0; mm < 128; mm++) {
                int m = m0 + mm;
                float4 wv = __ldg(reinterpret_cast<const float4*>(Wk2 + (size_t)m * DL) + d4);
                float q = sB[m - h * 512];
                acc.x += q*wv.x; acc.y += q*wv.y; acc.z += q*wv.z; acc.w += q*wv.w;
            }
            sP[part * 256 + d4] = acc;
        }
        __syncthreads();
        if (tid < 256) {
            float4 a = sP[tid];
#pragma unroll
            for (int p = 1; p < 4; p++) {
                float4 c = sP[p * 256 + tid];
                a.x += c.x; a.y += c.y; a.z += c.z; a.w += c.w;
            }
            reinterpret_cast<float4*>(g_pT2 + (size_t)idx * DL)[tid] = a;
        }
    }
}

// ---------------------------------------------------------------------------
// logits1 rows: l1[b][1+r] = t1[b] . x1[b][1+r][:]
// ---------------------------------------------------------------------------
__global__ __launch_bounds__(256) void k_logits1(const float* __restrict__ x1)
{
    int b = blockIdx.y;
    int w = threadIdx.x >> 5, lane = threadIdx.x & 31;
    const float4* t14 = reinterpret_cast<const float4*>(g_t1 + b * DM);
    float4 t0 = __ldg(&t14[lane]);
    float4 t1v = __ldg(&t14[lane + 32]);
    float4 t2v = __ldg(&t14[lane + 64]);
    float4 t3v = __ldg(&t14[lane + 96]);
#pragma unroll
    for (int j = 0; j < 8; j++) {
        int r = blockIdx.x * 64 + j * 8 + w;
        const float4* xr = reinterpret_cast<const float4*>(
            x1 + ((size_t)b * NMR + 1 + r) * DM);
        float s = dot4(__ldg(&xr[lane]),      t0)
                + dot4(__ldg(&xr[lane + 32]), t1v)
                + dot4(__ldg(&xr[lane + 64]), t2v)
                + dot4(__ldg(&xr[lane + 96]), t3v);
        s = wredsum(s);
        if (lane == 0) g_l1[b * NK1 + 1 + r] = s;
    }
}

// ---------------------------------------------------------------------------
// softmax1 per batch -> a1sT[n][b]
// ---------------------------------------------------------------------------
__global__ __launch_bounds__(256) void k_softmax1()
{
    __shared__ float red[8];
    int b = blockIdx.x, tid = threadIdx.x;
    float p = 0.f;
    for (int i = tid; i < DM; i += 256) p += g_t1[b*DM+i] * g_csp[b*DM+i];
    float l0 = block_sum8(p, red);
    float mx = -1e30f;
    for (int i = tid; i < NK1; i += 256) {
        float v = i ? g_l1[b*NK1+i] : l0;
        mx = fmaxf(mx, v);
    }
    mx = block_max8(mx, red);
    float se = 0.f;
    for (int i = tid; i < NK1; i += 256) {
        float v = i ? g_l1[b*NK1+i] : l0;
        se += __expf(v - mx);
    }
    se = block_sum8(se, red);
    float inv = 1.f / se;
    for (int i = tid; i < NK1; i += 256) {
        float v = i ? g_l1[b*NK1+i] : l0;
        g_a1sT[i * 16 + b] = __expf(v - mx) * inv;
    }
}

// ---------------------------------------------------------------------------
// att1 proj v2: a1p[b][m] = proj_b[m] + sum_n proj_w[m][n]*a1s[b][n].
// grid = (129, 2): y = batch half (8 batches in 32.8KB smem).
// Each warp computes 4 consecutive m rows so one smem a1 read feeds 4 FMAs.
// ---------------------------------------------------------------------------
__global__ __launch_bounds__(256) void k_proj(
    const float* __restrict__ proj_w, const float* __restrict__ proj_b)
{
    __shared__ float sA[NK1 * 8];          // [n][8 batches of this half]
    int tid = threadIdx.x, lane = tid & 31, warp = tid >> 5;
    int h = blockIdx.y;
    for (int i = tid; i < NK1 * 8; i += 256) {
        int n = i >> 3, j = i & 7;
        sA[i] = g_a1sT[n * 16 + h * 8 + j];
    }
    __syncthreads();
    int m0 = blockIdx.x * 32 + warp * 4;
    float acc[4][8];
#pragma unroll
    for (int r = 0; r < 4; r++)
#pragma unroll
        for (int j = 0; j < 8; j++) acc[r][j] = 0.f;
    for (int n = lane; n < NK1; n += 32) {
        float4 a0 = *reinterpret_cast<const float4*>(sA + n * 8);
        float4 a1 = *reinterpret_cast<const float4*>(sA + n * 8 + 4);
#pragma unroll
        for (int r = 0; r < 4; r++) {
            int m = m0 + r;
            float w = (m < NK2) ? __ldg(&proj_w[(size_t)m * NK1 + n]) : 0.f;
            acc[r][0] += w * a0.x; acc[r][1] += w * a0.y;
            acc[r][2] += w * a0.z; acc[r][3] += w * a0.w;
            acc[r][4] += w * a1.x; acc[r][5] += w * a1.y;
            acc[r][6] += w * a1.z; acc[r][7] += w * a1.w;
        }
    }
#pragma unroll
    for (int r = 0; r < 4; r++) {
        int m = m0 + r;
        float bias = (m < NK2) ? __ldg(&proj_b[m]) : 0.f;
#pragma unroll
        for (int j = 0; j < 8; j++) {
            float v = wredsum(acc[r][j]);
            if (lane == 0 && m < NK2)
                g_a1p[(size_t)(h * 8 + j) * NK2 + m] = v + bias;
        }
    }
}

// ---------------------------------------------------------------------------
// Streaming pass over x0 v2: 8 rows per barrier round (8 dots in flight,
// one smem exchange, then 8 sequential online-softmax updates).
// ---------------------------------------------------------------------------
__global__ __launch_bounds__(256) void k_stream(const float* __restrict__ x0)
{
    __shared__ float red[64];
    int b = blockIdx.y, g = blockIdx.x;
    int tid = threadIdx.x, lane = tid & 31, wid = tid >> 5;
    int r0 = g * RPB, r1 = min(r0 + RPB, NL);
    float4 e0 = __ldg(reinterpret_cast<const float4*>(g_pT2 + (size_t)(b*2+0) * DL) + tid);
    float4 e1 = __ldg(reinterpret_cast<const float4*>(g_pT2 + (size_t)(b*2+1) * DL) + tid);
    float4 t2v = make_float4((e0.x+e1.x)*INV32f, (e0.y+e1.y)*INV32f,
                             (e0.z+e1.z)*INV32f, (e0.w+e1.w)*INV32f);
    float m = -1e30f, z = 0.f;
    float4 ae = make_float4(0.f,0.f,0.f,0.f);
    float4 aa = make_float4(0.f,0.f,0.f,0.f);
    const float4* xb = reinterpret_cast<const float4*>(x0 + (size_t)b * NL * DL);
    for (int k = r0; k < r1; k += 8) {
        float4 rr[8]; float dd[8];
#pragma unroll
        for (int j = 0; j < 8; j++) {
            int kk = k + j;
            rr[j] = (kk < r1) ? __ldg(&xb[(size_t)kk * 256 + tid])
                              : make_float4(0.f,0.f,0.f,0.f);
        }
#pragma unroll
        for (int j = 0; j < 8; j++) dd[j] = wredsum(dot4(rr[j], t2v));
        if (lane < 8) red[lane * 8 + wid] = dd[lane];
        __syncthreads();
#pragma unroll
        for (int j = 0; j < 8; j++) {
            int kk = k + j;
            if (kk < r1) {
                const float* rj = red + j * 8;
                float l = rj[0]+rj[1]+rj[2]+rj[3]+rj[4]+rj[5]+rj[6]+rj[7];
                float a1 = __ldg(&g_a1p[b * NK2 + 1 + kk]);
                float nm = fmaxf(m, l);
                float sc = __expf(m - nm);
                float p  = __expf(l - nm);
                z = z * sc + p;
                ae.x = ae.x*sc + p*rr[j].x; ae.y = ae.y*sc + p*rr[j].y;
                ae.z = ae.z*sc + p*rr[j].z; ae.w = ae.w*sc + p*rr[j].w;
                aa.x += a1*rr[j].x; aa.y += a1*rr[j].y;
                aa.z += a1*rr[j].z; aa.w += a1*rr[j].w;
                m = nm;
            }
        }
        __syncthreads();
    }
    size_t o = ((size_t)b * GS + g) * DL + tid * 4;
    g_pe[o+0]=ae.x; g_pe[o+1]=ae.y; g_pe[o+2]=ae.z; g_pe[o+3]=ae.w;
    g_pa[o+0]=aa.x; g_pa[o+1]=aa.y; g_pa[o+2]=aa.z; g_pa[o+3]=aa.w;
    if (tid == 0) { g_pm[b*GS+g] = m; g_pz[b*GS+g] = z; }
}

// ---------------------------------------------------------------------------
// Fused epilogue (unchanged): combine -> s -> Wv.s -> partial gs
// ---------------------------------------------------------------------------
__global__ __launch_bounds__(1024) void k_final(
    const float* __restrict__ Wv, const float* __restrict__ gs_w)
{
    __shared__ float sS[1024];
    __shared__ float sO[512];
    __shared__ float red[32];
    __shared__ float ws[GS];
    int tid = threadIdx.x, lane = tid & 31, w = tid >> 5;
    int b = blockIdx.x >> 1, h = blockIdx.x & 1;

    float t2d = (__ldg(&g_pT2[(size_t)(b*2+0)*DL + tid]) +
                 __ldg(&g_pT2[(size_t)(b*2+1)*DL + tid])) * INV32f;
    float cv = __ldg(&g_cmp[b * DL + tid]);
    float p = t2d * cv;
    p = wredsum(p);
    if (lane == 0) red[w] = p;
    __syncthreads();
    if (w == 0) {
        float t = red[lane];
        t = wredsum(t);
        if (lane == 0) red[0] = t;
    }
    __syncthreads();
    float l2c = red[0];
    float M = l2c;
#pragma unroll 8
    for (int g = 0; g < GS; g++) M = fmaxf(M, __ldg(&g_pm[b*GS+g]));
    if (tid < GS) ws[tid] = __expf(g_pm[b*GS+tid] - M);
    __syncthreads();
    float ecls = __expf(l2c - M);
    float Z = ecls;
#pragma unroll 8
    for (int g = 0; g < GS; g++) Z += ws[g] * __ldg(&g_pz[b*GS+g]);
    float se = 0.f, sa = 0.f;
    for (int g = 0; g < GS; g++) {
        size_t o = ((size_t)b * GS + g) * DL + tid;
        se += ws[g] * __ldg(&g_pe[o]);
        sa += __ldg(&g_pa[o]);
    }
    float a10 = __ldg(&g_a1p[b * NK2]);
    se += ecls * cv;
    sa += a10 * cv;
    sS[tid] = 0.3f * sa + 0.7f * se / Z;
    __syncthreads();
    {
        const float4* s4 = reinterpret_cast<const float4*>(sS);
        float4 xv[8];
#pragma unroll
        for (int k = 0; k < 8; k++) xv[k] = s4[lane + 32 * k];
        for (int m = h * 512 + w; m < h * 512 + 512; m += 32) {
            const float4* wr = reinterpret_cast<const float4*>(Wv + (size_t)m * DL);
            float d = 0.f;
#pragma unroll
            for (int k = 0; k < 8; k++) d += dot4(__ldg(&wr[lane + 32 * k]), xv[k]);
            d = wredsum(d);
            if (lane == 0) sO[m - h * 512] = d;
        }
    }
    __syncthreads();
    {
        const float4* s4 = reinterpret_cast<const float4*>(sO);
        float4 xv[4];
#pragma unroll
        for (int k = 0; k < 4; k++) xv[k] = s4[lane + 32 * k];
        for (int m = w; m < DS; m += 32) {
            const float4* wr = reinterpret_cast<const float4*>(
                gs_w + (size_t)m * DL + h * 512);
            float d = 0.f;
#pragma unroll
            for (int k = 0; k < 4; k++) d += dot4(__ldg(&wr[lane + 32 * k]), xv[k]);
            d = wredsum(d);
            if (lane == 0) g_pgs[(size_t)(b*2+h) * DS + m] = d;
        }
    }
}

// ---------------------------------------------------------------------------
// Broadcast write v2: grid (x, 16); per-thread broadcast value is
// loop-invariant (stride divisible by 64 float4), so hoist to registers
// and emit a pure STG.128 stream.
// ---------------------------------------------------------------------------
__global__ __launch_bounds__(256) void k_write(float4* __restrict__ out,
                                               const float* __restrict__ gs_b)
{
    int b = blockIdx.y;
    const float4* p4 = reinterpret_cast<const float4*>(g_pgs);
    const float4* b4 = reinterpret_cast<const float4*>(gs_b);
    unsigned per = (unsigned)NL * 64;             // float4 per batch
    unsigned i0 = blockIdx.x * 256 + threadIdx.x;
    unsigned d4 = i0 & 63;
    float4 v0 = __ldg(&p4[(b * 2 + 0) * 64 + d4]);
    float4 v1 = __ldg(&p4[(b * 2 + 1) * 64 + d4]);
    float4 bb = __ldg(&b4[d4]);
    float4 v = make_float4(v0.x + v1.x + bb.x, v0.y + v1.y + bb.y,
                           v0.z + v1.z + bb.z, v0.w + v1.w + bb.w);
    float4* ob = out + (size_t)b * per;
    unsigned stride = gridDim.x * 256;            // multiple of 64
    for (unsigned i = i0; i < per; i += stride) ob[i] = v;
}

// ---------------------------------------------------------------------------
extern "C" void kernel_launch(void* const* d_in, const int* in_sizes, int n_in,
                              void* d_out, int out_size)
{
    const float* x0     = (const float*)d_in[0];
    const float* x1     = (const float*)d_in[1];
    const float* x2     = (const float*)d_in[2];
    const float* f_s_w  = (const float*)d_in[3];
    const float* f_s_b  = (const float*)d_in[4];
    const float* f_m_w  = (const float*)d_in[5];
    const float* f_m_b  = (const float*)d_in[6];
    const float* Wq1    = (const float*)d_in[7];
    const float* Wk1    = (const float*)d_in[8];
    const float* Wq2    = (const float*)d_in[9];
    const float* Wk2    = (const float*)d_in[10];
    const float* Wv     = (const float*)d_in[11];
    const float* proj_w = (const float*)d_in[12];
    const float* proj_b = (const float*)d_in[13];
    const float* gs_w   = (const float*)d_in[14];
    const float* gs_b   = (const float*)d_in[15];

    k_pro<<<48, 1024>>>(x1, x2, f_s_w, f_s_b, f_m_w, f_m_b, Wq1, Wk1, Wq2, Wk2);
    k_logits1<<<dim3(16, NB), 256>>>(x1);
    k_softmax1<<<NB, 256>>>();
    k_proj<<<dim3(129, 2), 256>>>(proj_w, proj_b);
    k_stream<<<dim3(GS, NB), 256>>>(x0);
    k_final<<<2 * NB, 1024>>>(Wv, gs_w);
    k_write<<<dim3(512, NB), 256>>>((float4*)d_out, gs_b);
}